// round 15
// baseline (speedup 1.0000x reference)
#include <cuda_runtime.h>
#include <cuda_bf16.h>
#include <cuda_fp8.h>
#include <cstdint>

#define NSITES   50000
#define NPERM    12
#define NNEIGH   8
#define INF      512
#define OUTF     64
#define LN2F     0.6931471805599453f
#define LOSCALE  8192.0f                    // 2^13

#define TOTROWS  (NSITES * NPERM)           // 600000
#define BM       128
#define NBLOCKS  ((TOTROWS + BM - 1) / BM)  // 4688
#define NTHREADS 256
#define NCHUNK   8

// ---------------- SMEM layout (bytes, dynamic) ----------------
#define SM_BIAS  0                          // 256 B
#define SM_IDX   256                        // 4096 B
#define SM_W     4608                       // 2 bufs x (hi 8192 + h8 4096 + l8 4096)
#define WBUF     16384
#define SM_A     37376                      // 2 bufs x (hi 16384 + h8 8192 + l8 8192)
#define ABUF     32768
#define SM_TOTAL 102912
#define SM_RED   SM_A                       // epilogue reuse: 128*64 f32 = 32768 B

// ---------------- global split buffers ----------------
__device__ __nv_bfloat16 g_Whi[NCHUNK * 64 * 64];   // bf16 hi  [c][n][kk]
__device__ uint8_t       g_Wh8[NCHUNK * 64 * 64];   // e4m3(w)
__device__ uint8_t       g_Wl8[NCHUNK * 64 * 64];   // e4m3((w-hi)*2^13)
__device__ __nv_bfloat16 g_Xhi[NSITES * 64];
__device__ uint8_t       g_Xh8[NSITES * 64];
__device__ uint8_t       g_Xl8[NSITES * 64];

// ---------------- pre-kernels ----------------
__global__ void split_W_kernel(const float* __restrict__ W) {
    int i = blockIdx.x * blockDim.x + threadIdx.x;
    if (i < OUTF * INF) {
        int n = i >> 9, k = i & 511, c = k >> 6, kk = k & 63;
        float v = W[i];
        __nv_bfloat16 h = __float2bfloat16(v);
        float r = v - __bfloat162float(h);
        int j = c * 4096 + n * 64 + kk;
        g_Whi[j] = h;
        __nv_fp8_e4m3 h8(v), l8(r * LOSCALE);
        g_Wh8[j] = *(uint8_t*)&h8;
        g_Wl8[j] = *(uint8_t*)&l8;
    }
}
__global__ void split_X_kernel(const float* __restrict__ X) {
    int i = blockIdx.x * blockDim.x + threadIdx.x;
    if (i < NSITES * 64) {
        float v = X[i];
        __nv_bfloat16 h = __float2bfloat16(v);
        float r = v - __bfloat162float(h);
        g_Xhi[i] = h;
        __nv_fp8_e4m3 h8(v), l8(r * LOSCALE);
        g_Xh8[i] = *(uint8_t*)&h8;
        g_Xl8[i] = *(uint8_t*)&l8;
    }
}
__global__ void zero_out_kernel(float* __restrict__ out) {
    int i = blockIdx.x * blockDim.x + threadIdx.x;
    if (i < NSITES * OUTF) out[i] = 0.0f;
}

// ---------------- PTX helpers ----------------
__device__ __forceinline__ uint32_t smem_u32(const void* p) {
    uint32_t a;
    asm("{ .reg .u64 t; cvta.to.shared.u64 t, %1; cvt.u32.u64 %0, t; }" : "=r"(a) : "l"(p));
    return a;
}
__device__ __forceinline__ void cp16(uint32_t dst, const void* src) {
    asm volatile("cp.async.cg.shared.global [%0], [%1], 16;" :: "r"(dst), "l"(src) : "memory");
}
#define CP_COMMIT() asm volatile("cp.async.commit_group;" ::: "memory")
#define CP_WAIT0()  asm volatile("cp.async.wait_group 0;" ::: "memory")
__device__ __forceinline__ void mma_bf16(float* d, const uint32_t* a,
                                         uint32_t b0, uint32_t b1) {
    asm volatile(
        "mma.sync.aligned.m16n8k16.row.col.f32.bf16.bf16.f32 "
        "{%0,%1,%2,%3}, {%4,%5,%6,%7}, {%8,%9}, {%0,%1,%2,%3};\n"
        : "+f"(d[0]), "+f"(d[1]), "+f"(d[2]), "+f"(d[3])
        : "r"(a[0]), "r"(a[1]), "r"(a[2]), "r"(a[3]), "r"(b0), "r"(b1));
}
__device__ __forceinline__ void mma_e4m3(float* d, const uint32_t* a,
                                         uint32_t b0, uint32_t b1) {
    asm volatile(
        "mma.sync.aligned.m16n8k32.row.col.f32.e4m3.e4m3.f32 "
        "{%0,%1,%2,%3}, {%4,%5,%6,%7}, {%8,%9}, {%0,%1,%2,%3};\n"
        : "+f"(d[0]), "+f"(d[1]), "+f"(d[2]), "+f"(d[3])
        : "r"(a[0]), "r"(a[1]), "r"(a[2]), "r"(a[3]), "r"(b0), "r"(b1));
}
#define LDSM_X4(R, A) \
    asm volatile("ldmatrix.sync.aligned.m8n8.x4.shared.b16 {%0,%1,%2,%3}, [%4];" \
        : "=r"((R)[0]), "=r"((R)[1]), "=r"((R)[2]), "=r"((R)[3]) : "r"(A))

// ---------------- main kernel ----------------
__global__ __launch_bounds__(NTHREADS, 2)
void lcnn_mma_kernel(const int* __restrict__ NS,
                     const float* __restrict__ bias,
                     float* __restrict__ out)
{
    extern __shared__ char smem[];
    const int tid = threadIdx.x;
    const int wid = tid >> 5;     // 0..7
    const int lid = tid & 31;
    const int g   = lid >> 2;     // 0..7
    const int tg  = lid & 3;      // 0..3
    const int wm  = wid >> 1;     // 0..3 : warp row block (32 rows)
    const int wn  = wid & 1;      // 0..1 : warp col block (32 cols)
    const int blk = blockIdx.x;

    const int R0    = blk * BM;
    const int valid = min(BM, TOTROWS - R0);

    if (tid < OUTF) *(float*)(smem + SM_BIAS + tid * 4) = bias[tid];

    int* idx_sm = (int*)(smem + SM_IDX);
    for (int i = tid; i < BM * NNEIGH; i += NTHREADS)
        idx_sm[i] = (i < valid * NNEIGH) ? NS[(long)R0 * NNEIGH + i] : 0;
    __syncthreads();     // idx visible before first gather

    const uint4* Xhi4 = (const uint4*)g_Xhi;
    const uint4* Xh84 = (const uint4*)g_Xh8;
    const uint4* Xl84 = (const uint4*)g_Xl8;
    const uint4* GWh4 = (const uint4*)g_Whi;
    const uint4* GW8h = (const uint4*)g_Wh8;
    const uint4* GW8l = (const uint4*)g_Wl8;

    const uint32_t A0 = smem_u32(smem + SM_A);
    const uint32_t W0 = smem_u32(smem + SM_W);

    // ---- bf16 ldmatrix lane constants (128-B rows, xor = (row&7)*16) ----
    const uint32_t xorv  = (uint32_t)((lid & 7) * 16);
    const uint32_t aksel = (uint32_t)(((lid >> 4) & 1) * 16);
    const uint32_t wksel = (uint32_t)(((lid >> 3) & 1) * 16);
    const uint32_t arow0 = (uint32_t)((wm * 32 + ((lid >> 3) & 1) * 8 + (lid & 7)) * 128);
    const uint32_t arow1 = arow0 + 16 * 128;
    const uint32_t wrow0 = (uint32_t)((wn * 32 + ((lid >> 4) & 1) * 8 + (lid & 7)) * 128);
    const uint32_t wrow1 = wrow0 + 16 * 128;

    // ---- fp8 ldmatrix lane constants (64-B rows, xor = ((row>>1)&3)*16) ----
    // A fp8: bit3 -> row+8, bit4 -> k+16  => R0..R3 = a0..a3 of m16n8k32
    const int ra8 = wm * 32 + ((lid >> 3) & 1) * 8 + (lid & 7);
    const uint32_t xor8a  = (uint32_t)(((ra8 >> 1) & 3) * 16);   // same for both mt
    const uint32_t a8r0   = (uint32_t)(ra8 * 64);
    const uint32_t a8r1   = a8r0 + 16 * 64;
    const uint32_t aksel8 = (uint32_t)(((lid >> 4) & 1) * 16);
    // W fp8: bit4 -> n+8, bit3 -> k+16  => {R0,R1}=b0,b1 of n8-tile0; {R2,R3}=tile1
    const int rn8 = wn * 32 + ((lid >> 4) & 1) * 8 + (lid & 7);
    const uint32_t xor8w  = (uint32_t)(((rn8 >> 1) & 3) * 16);   // same for both nt16
    const uint32_t w8r0   = (uint32_t)(rn8 * 64);
    const uint32_t w8r1   = w8r0 + 16 * 64;
    const uint32_t wksel8 = (uint32_t)(((lid >> 3) & 1) * 16);

    float acch[2][4][4], accl[2][4][4];
    #pragma unroll
    for (int mt = 0; mt < 2; mt++)
        #pragma unroll
        for (int nt = 0; nt < 4; nt++)
            #pragma unroll
            for (int e = 0; e < 4; e++) {
                acch[mt][nt][e] = 0.0f;
                accl[mt][nt][e] = 0.0f;
            }

    // stage chunk c into buffer b via cp.async (one commit group, 12 cp16/thread)
    auto stage = [&](int c, int b) {
        const uint32_t Ah  = A0 + b * ABUF;
        const uint32_t A8h = Ah + 16384, A8l = Ah + 24576;
        const uint32_t Wh  = W0 + b * WBUF;
        const uint32_t W8h = Wh + 8192,  W8l = Wh + 12288;
        #pragma unroll
        for (int it = 0; it < 4; it++) {            // A hi bf16: 1024 cp16
            int linear = tid + it * NTHREADS;
            int m = linear >> 3, u = linear & 7;
            int nb = idx_sm[m * NNEIGH + c];
            uint32_t off = (uint32_t)(m * 128) +
                           ((uint32_t)(u * 16) ^ (uint32_t)((m & 7) * 16));
            cp16(Ah + off, Xhi4 + nb * 8 + u);
        }
        #pragma unroll
        for (int it = 0; it < 2; it++) {            // A fp8 hi+lo: 512 cp16 each
            int linear = tid + it * NTHREADS;
            int m = linear >> 2, u = linear & 3;
            int nb = idx_sm[m * NNEIGH + c];
            uint32_t off = (uint32_t)(m * 64) +
                           ((uint32_t)(u * 16) ^ (uint32_t)(((m >> 1) & 3) * 16));
            cp16(A8h + off, Xh84 + nb * 4 + u);
            cp16(A8l + off, Xl84 + nb * 4 + u);
        }
        #pragma unroll
        for (int it = 0; it < 2; it++) {            // W hi bf16: 512 cp16
            int v = tid + it * NTHREADS;
            int n = v >> 3, uu = v & 7;
            uint32_t off = (uint32_t)(n * 128) +
                           ((uint32_t)(uu * 16) ^ (uint32_t)((n & 7) * 16));
            cp16(Wh + off, GWh4 + c * 512 + v);
        }
        {                                           // W fp8 hi+lo: 256 cp16 each
            int v = tid;
            int n = v >> 2, uu = v & 3;
            uint32_t off = (uint32_t)(n * 64) +
                           ((uint32_t)(uu * 16) ^ (uint32_t)(((n >> 1) & 3) * 16));
            cp16(W8h + off, GW8h + c * 256 + v);
            cp16(W8l + off, GW8l + c * 256 + v);
        }
        CP_COMMIT();
    };

    stage(0, 0);

    for (int c = 0; c < NCHUNK; c++) {
        const int b = c & 1;
        CP_WAIT0();
        __syncthreads();
        if (c + 1 < NCHUNK) stage(c + 1, 1 - b);   // overlaps MMA below

        const uint32_t Ahc  = A0 + b * ABUF;
        const uint32_t A8hc = Ahc + 16384, A8lc = Ahc + 24576;
        const uint32_t Whc  = W0 + b * WBUF;
        const uint32_t W8hc = Whc + 8192,  W8lc = Whc + 12288;

        // ---- hi pass: bf16 Ah*Bh, 4 k16 steps ----
        #pragma unroll
        for (int ks = 0; ks < 4; ks++) {
            const uint32_t ka = ((uint32_t)(ks * 32) + aksel) ^ xorv;
            const uint32_t kw = ((uint32_t)(ks * 32) + wksel) ^ xorv;
            uint32_t ah[2][4], bh[2][4];
            LDSM_X4(ah[0], Ahc + arow0 + ka);
            LDSM_X4(ah[1], Ahc + arow1 + ka);
            LDSM_X4(bh[0], Whc + wrow0 + kw);
            LDSM_X4(bh[1], Whc + wrow1 + kw);
            #pragma unroll
            for (int mt = 0; mt < 2; mt++)
                #pragma unroll
                for (int np = 0; np < 2; np++) {
                    mma_bf16(acch[mt][np * 2 + 0], ah[mt], bh[np][0], bh[np][1]);
                    mma_bf16(acch[mt][np * 2 + 1], ah[mt], bh[np][2], bh[np][3]);
                }
        }

        // ---- lo passes: e4m3, 2 k32 steps: A8*(Bl*2^13) + (Al*2^13)*B8 ----
        #pragma unroll
        for (int s = 0; s < 2; s++) {
            const uint32_t ka8 = ((uint32_t)(s * 32) + aksel8) ^ xor8a;
            const uint32_t kw8 = ((uint32_t)(s * 32) + wksel8) ^ xor8w;
            uint32_t a8h[2][4], a8l[2][4], b8h[2][4], b8l[2][4];
            LDSM_X4(a8h[0], A8hc + a8r0 + ka8);
            LDSM_X4(a8h[1], A8hc + a8r1 + ka8);
            LDSM_X4(a8l[0], A8lc + a8r0 + ka8);
            LDSM_X4(a8l[1], A8lc + a8r1 + ka8);
            LDSM_X4(b8l[0], W8lc + w8r0 + kw8);
            LDSM_X4(b8l[1], W8lc + w8r1 + kw8);
            LDSM_X4(b8h[0], W8hc + w8r0 + kw8);
            LDSM_X4(b8h[1], W8hc + w8r1 + kw8);
            #pragma unroll
            for (int mt = 0; mt < 2; mt++)
                #pragma unroll
                for (int nt = 0; nt < 2; nt++)
                    #pragma unroll
                    for (int j = 0; j < 2; j++) {
                        mma_e4m3(accl[mt][nt * 2 + j], a8h[mt],
                                 b8l[nt][j * 2], b8l[nt][j * 2 + 1]);
                        mma_e4m3(accl[mt][nt * 2 + j], a8l[mt],
                                 b8h[nt][j * 2], b8h[nt][j * 2 + 1]);
                    }
        }
    }

    // Epilogue: merge hi + lo*2^-13, bias + shifted softplus -> smem red buffer
    float* red = (float*)(smem + SM_RED);
    const float* bsm = (const float*)(smem + SM_BIAS);
    const float inv = 1.0f / LOSCALE;
    #pragma unroll
    for (int mt = 0; mt < 2; mt++) {
        const int row0 = wm * 32 + mt * 16 + g;
        #pragma unroll
        for (int nt = 0; nt < 4; nt++) {
            const int col = wn * 32 + nt * 8 + 2 * tg;
            const float b0 = bsm[col], b1 = bsm[col + 1];
            float x, s0, s1;
            x = acch[mt][nt][0] + accl[mt][nt][0] * inv + b0;
            s0 = fmaxf(x, 0.0f) + __logf(1.0f + __expf(-fabsf(x))) - LN2F;
            x = acch[mt][nt][1] + accl[mt][nt][1] * inv + b1;
            s1 = fmaxf(x, 0.0f) + __logf(1.0f + __expf(-fabsf(x))) - LN2F;
            *(float2*)&red[row0 * 64 + col] = make_float2(s0, s1);
            x = acch[mt][nt][2] + accl[mt][nt][2] * inv + b0;
            s0 = fmaxf(x, 0.0f) + __logf(1.0f + __expf(-fabsf(x))) - LN2F;
            x = acch[mt][nt][3] + accl[mt][nt][3] * inv + b1;
            s1 = fmaxf(x, 0.0f) + __logf(1.0f + __expf(-fabsf(x))) - LN2F;
            *(float2*)&red[(row0 + 8) * 64 + col] = make_float2(s0, s1);
        }
    }
    __syncthreads();

    // Per-site perm sums. Sites can straddle tile boundaries -> <=2 atomic
    // contributions per output; float add of 2 terms is order-independent.
    {
        int s0 = R0 / NPERM;
        int s1 = (R0 + valid - 1) / NPERM;
        int nout = (s1 - s0 + 1) * OUTF;
        for (int i = tid; i < nout; i += NTHREADS) {
            int site = s0 + (i >> 6);
            int col  = i & 63;
            int rbeg = max(site * NPERM, R0);
            int rend = min(site * NPERM + NPERM, R0 + valid);
            float v = 0.0f;
            for (int r = rbeg; r < rend; r++)
                v += red[(r - R0) * 64 + col];
            atomicAdd(&out[(long)site * OUTF + col], v);
        }
    }
}

extern "C" void kernel_launch(void* const* d_in, const int* in_sizes, int n_in,
                              void* d_out, int out_size) {
    const float* X  = (const float*)d_in[0];   // X_sites (50000,64) f32
    const int*   NS = (const int*)  d_in[1];   // X_NSs   (50000,12,8) i32
    const float* W  = (const float*)d_in[2];   // W       (64,512) f32
    const float* b  = (const float*)d_in[3];   // b       (64,) f32
    float* out = (float*)d_out;                // (50000,64) f32

    cudaFuncSetAttribute(lcnn_mma_kernel,
                         cudaFuncAttributeMaxDynamicSharedMemorySize, SM_TOTAL);

    split_W_kernel<<<(OUTF * INF + 255) / 256, 256>>>(W);
    split_X_kernel<<<(NSITES * 64 + 255) / 256, 256>>>(X);
    zero_out_kernel<<<(NSITES * OUTF + 255) / 256, 256>>>(out);
    lcnn_mma_kernel<<<NBLOCKS, NTHREADS, SM_TOTAL>>>(NS, b, out);
}

// round 16
// speedup vs baseline: 1.3212x; 1.3212x over previous
#include <cuda_runtime.h>
#include <cuda_bf16.h>
#include <cstdint>

#define NSITES   50000
#define NPERM    12
#define NNEIGH   8
#define INF      512
#define OUTF     64
#define LN2F     0.6931471805599453f

#define TOTROWS  (NSITES * NPERM)                  // 600000
#define BM       128
#define NBLOCKS  ((TOTROWS + BM - 1) / BM)         // 4688
#define NTHREADS 256
#define NCHUNK   8

// ---------------- SMEM layout (bytes, dynamic) ----------------
#define SM_BIAS  0                      // 64 f32 = 256 B
#define SM_IDX   256                    // 128*8 int = 4096 B
#define SM_W     5120                   // 2 bufs x (hi 8192 + lo 8192)
#define WBUF     16384
#define SM_A     38912                  // 2 bufs x (hi 16384 + lo 16384)
#define ABUF     32768
#define SM_TOTAL 104448
#define SM_RED   SM_A                   // epilogue reuse: 128*64 f32 = 32768 B

// ---------------- global split buffers ----------------
__device__ __nv_bfloat16 g_Whi[NCHUNK * 64 * 64];   // [c][n][kk], kk contiguous
__device__ __nv_bfloat16 g_Wlo[NCHUNK * 64 * 64];
__device__ __nv_bfloat16 g_Xhi[NSITES * 64];
__device__ __nv_bfloat16 g_Xlo[NSITES * 64];

// ---------------- pre-kernels ----------------
__global__ void split_W_kernel(const float* __restrict__ W) {
    int i = blockIdx.x * blockDim.x + threadIdx.x;
    if (i < OUTF * INF) {
        int n = i >> 9, k = i & 511, c = k >> 6, kk = k & 63;
        float v = W[i];
        __nv_bfloat16 h = __float2bfloat16(v);
        float r = v - __bfloat162float(h);
        int j = c * 4096 + n * 64 + kk;
        g_Whi[j] = h;
        g_Wlo[j] = __float2bfloat16(r);
    }
}
__global__ void split_X_kernel(const float* __restrict__ X) {
    int i = blockIdx.x * blockDim.x + threadIdx.x;
    if (i < NSITES * 64) {
        float v = X[i];
        __nv_bfloat16 h = __float2bfloat16(v);
        g_Xhi[i] = h;
        g_Xlo[i] = __float2bfloat16(v - __bfloat162float(h));
    }
}
__global__ void zero_out_kernel(float* __restrict__ out) {
    int i = blockIdx.x * blockDim.x + threadIdx.x;
    if (i < NSITES * OUTF) out[i] = 0.0f;
}

// ---------------- PTX helpers ----------------
__device__ __forceinline__ uint32_t smem_u32(const void* p) {
    uint32_t a;
    asm("{ .reg .u64 t; cvta.to.shared.u64 t, %1; cvt.u32.u64 %0, t; }" : "=r"(a) : "l"(p));
    return a;
}
__device__ __forceinline__ void cp16(uint32_t dst, const void* src) {
    asm volatile("cp.async.cg.shared.global [%0], [%1], 16;" :: "r"(dst), "l"(src) : "memory");
}
#define CP_COMMIT() asm volatile("cp.async.commit_group;" ::: "memory")
#define CP_WAIT0()  asm volatile("cp.async.wait_group 0;" ::: "memory")
__device__ __forceinline__ void mma_bf16(float* d, const uint32_t* a,
                                         uint32_t b0, uint32_t b1) {
    asm volatile(
        "mma.sync.aligned.m16n8k16.row.col.f32.bf16.bf16.f32 "
        "{%0,%1,%2,%3}, {%4,%5,%6,%7}, {%8,%9}, {%0,%1,%2,%3};\n"
        : "+f"(d[0]), "+f"(d[1]), "+f"(d[2]), "+f"(d[3])
        : "r"(a[0]), "r"(a[1]), "r"(a[2]), "r"(a[3]), "r"(b0), "r"(b1));
}
#define LDSM_X4(R, A) \
    asm volatile("ldmatrix.sync.aligned.m8n8.x4.shared.b16 {%0,%1,%2,%3}, [%4];" \
        : "=r"((R)[0]), "=r"((R)[1]), "=r"((R)[2]), "=r"((R)[3]) : "r"(A))

// ---------------- main kernel ----------------
__global__ __launch_bounds__(NTHREADS)
void lcnn_mma_kernel(const int* __restrict__ NS,
                     const float* __restrict__ bias,
                     float* __restrict__ out)
{
    extern __shared__ char smem[];
    const int tid = threadIdx.x;
    const int wid = tid >> 5;     // 0..7
    const int lid = tid & 31;
    const int g   = lid >> 2;     // 0..7
    const int tg  = lid & 3;      // 0..3
    const int wm  = wid >> 1;     // 0..3 : warp row block (32 rows)
    const int wn  = wid & 1;      // 0..1 : warp col block (32 cols)
    const int blk = blockIdx.x;

    const int R0    = blk * BM;
    const int valid = min(BM, TOTROWS - R0);

    if (tid < OUTF) *(float*)(smem + SM_BIAS + tid * 4) = bias[tid];

    int* idx_sm = (int*)(smem + SM_IDX);
    for (int i = tid; i < BM * NNEIGH; i += NTHREADS)
        idx_sm[i] = (i < valid * NNEIGH) ? NS[(long)R0 * NNEIGH + i] : 0;
    __syncthreads();     // idx visible before first gather

    const uint4* Xhi4 = (const uint4*)g_Xhi;
    const uint4* Xlo4 = (const uint4*)g_Xlo;
    const uint4* GWh4 = (const uint4*)g_Whi;
    const uint4* GWl4 = (const uint4*)g_Wlo;

    const uint32_t A0 = smem_u32(smem + SM_A);
    const uint32_t W0 = smem_u32(smem + SM_W);

    // ---- hoisted staging constants (loop-invariant across chunks) ----
    uint32_t offA[4];   // swizzled smem offsets for the 4 A cp16 per thread
    const int* idxp[4]; // per-slot pointer into idx row (idx changes only via [c])
    int      srcu[4];   // uint4 index within the gathered X row
    #pragma unroll
    for (int it = 0; it < 4; it++) {
        int linear = tid + it * NTHREADS;     // < 1024
        int m = linear >> 3, u = linear & 7;
        offA[it] = (uint32_t)(m * 128) +
                   ((uint32_t)(u * 16) ^ (uint32_t)((m & 7) * 16));
        idxp[it] = idx_sm + m * NNEIGH;
        srcu[it] = u;
    }
    uint32_t offW[2];
    int      wsrc[2];
    #pragma unroll
    for (int it = 0; it < 2; it++) {
        int v = tid + it * NTHREADS;          // < 512
        int n = v >> 3, uu = v & 7;
        offW[it] = (uint32_t)(n * 128) +
                   ((uint32_t)(uu * 16) ^ (uint32_t)((n & 7) * 16));
        wsrc[it] = v;
    }

    // ---- hoisted ldmatrix lane constants (swizzle xor is per-lane constant) ----
    const uint32_t xorv  = (uint32_t)((lid & 7) * 16);
    const uint32_t aksel = (uint32_t)(((lid >> 4) & 1) * 16);
    const uint32_t wksel = (uint32_t)(((lid >> 3) & 1) * 16);
    const uint32_t arow0 = (uint32_t)((wm * 32 + ((lid >> 3) & 1) * 8 + (lid & 7)) * 128);
    const uint32_t arow1 = arow0 + 16 * 128;
    const uint32_t wrow0 = (uint32_t)((wn * 32 + ((lid >> 4) & 1) * 8 + (lid & 7)) * 128);
    const uint32_t wrow1 = wrow0 + 16 * 128;

    float acc[2][4][4];
    #pragma unroll
    for (int mt = 0; mt < 2; mt++)
        #pragma unroll
        for (int nt = 0; nt < 4; nt++)
            #pragma unroll
            for (int e = 0; e < 4; e++)
                acc[mt][nt][e] = 0.0f;

    // stage chunk c into buffer b via cp.async (one commit group)
    auto stage = [&](int c, int b) {
        const uint32_t Ah = A0 + b * ABUF, Al = Ah + 16384;
        const uint32_t Wh = W0 + b * WBUF, Wl = Wh + 8192;
        #pragma unroll
        for (int it = 0; it < 4; it++) {
            int nb = idxp[it][c];
            cp16(Ah + offA[it], Xhi4 + nb * 8 + srcu[it]);
            cp16(Al + offA[it], Xlo4 + nb * 8 + srcu[it]);
        }
        #pragma unroll
        for (int it = 0; it < 2; it++) {
            cp16(Wh + offW[it], GWh4 + c * 512 + wsrc[it]);
            cp16(Wl + offW[it], GWl4 + c * 512 + wsrc[it]);
        }
        CP_COMMIT();
    };

    stage(0, 0);

    for (int c = 0; c < NCHUNK; c++) {
        const int b = c & 1;
        CP_WAIT0();          // chunk c copies (this thread) complete
        __syncthreads();     // all threads' copies visible; all done with MMA c-1
        if (c + 1 < NCHUNK) stage(c + 1, 1 - b);   // overlaps MMA below

        const uint32_t Ahc = A0 + b * ABUF;
        const uint32_t Alc = Ahc + 16384;
        const uint32_t Whc = W0 + b * WBUF;
        const uint32_t Wlc = Whc + 8192;

        // A-fragment pipeline: prefetch ks=0, then per ks prefetch ks+1
        uint32_t ahp[2][2][4], alp[2][2][4];   // [stage][mt][4]
        {
            const uint32_t ka0 = (aksel) ^ xorv;
            LDSM_X4(ahp[0][0], Ahc + arow0 + ka0);
            LDSM_X4(ahp[0][1], Ahc + arow1 + ka0);
            LDSM_X4(alp[0][0], Alc + arow0 + ka0);
            LDSM_X4(alp[0][1], Alc + arow1 + ka0);
        }
        #pragma unroll
        for (int ks = 0; ks < 4; ks++) {
            const int cur = ks & 1, nxt = cur ^ 1;
            if (ks + 1 < 4) {
                const uint32_t kan = ((uint32_t)((ks + 1) * 32) + aksel) ^ xorv;
                LDSM_X4(ahp[nxt][0], Ahc + arow0 + kan);
                LDSM_X4(ahp[nxt][1], Ahc + arow1 + kan);
                LDSM_X4(alp[nxt][0], Alc + arow0 + kan);
                LDSM_X4(alp[nxt][1], Alc + arow1 + kan);
            }
            const uint32_t kw = ((uint32_t)(ks * 32) + wksel) ^ xorv;
            uint32_t bh[2][4], bl[2][4];
            LDSM_X4(bh[0], Whc + wrow0 + kw);
            LDSM_X4(bh[1], Whc + wrow1 + kw);
            LDSM_X4(bl[0], Wlc + wrow0 + kw);
            LDSM_X4(bl[1], Wlc + wrow1 + kw);
            #pragma unroll
            for (int mt = 0; mt < 2; mt++) {
                #pragma unroll
                for (int np = 0; np < 2; np++) {
                    mma_bf16(acc[mt][np * 2 + 0], ahp[cur][mt], bh[np][0], bh[np][1]);
                    mma_bf16(acc[mt][np * 2 + 1], ahp[cur][mt], bh[np][2], bh[np][3]);
                    mma_bf16(acc[mt][np * 2 + 0], ahp[cur][mt], bl[np][0], bl[np][1]);
                    mma_bf16(acc[mt][np * 2 + 1], ahp[cur][mt], bl[np][2], bl[np][3]);
                    mma_bf16(acc[mt][np * 2 + 0], alp[cur][mt], bh[np][0], bh[np][1]);
                    mma_bf16(acc[mt][np * 2 + 1], alp[cur][mt], bh[np][2], bh[np][3]);
                }
            }
        }
    }

    // Epilogue: bias + shifted softplus -> smem red buffer [128][64] f32.
    float* red = (float*)(smem + SM_RED);
    const float* bsm = (const float*)(smem + SM_BIAS);
    #pragma unroll
    for (int mt = 0; mt < 2; mt++) {
        const int row0 = wm * 32 + mt * 16 + g;
        #pragma unroll
        for (int nt = 0; nt < 4; nt++) {
            const int col = wn * 32 + nt * 8 + 2 * tg;
            const float b0 = bsm[col], b1 = bsm[col + 1];
            float x, s0, s1;
            x = acc[mt][nt][0] + b0;
            s0 = fmaxf(x, 0.0f) + __logf(1.0f + __expf(-fabsf(x))) - LN2F;
            x = acc[mt][nt][1] + b1;
            s1 = fmaxf(x, 0.0f) + __logf(1.0f + __expf(-fabsf(x))) - LN2F;
            *(float2*)&red[row0 * 64 + col] = make_float2(s0, s1);
            x = acc[mt][nt][2] + b0;
            s0 = fmaxf(x, 0.0f) + __logf(1.0f + __expf(-fabsf(x))) - LN2F;
            x = acc[mt][nt][3] + b1;
            s1 = fmaxf(x, 0.0f) + __logf(1.0f + __expf(-fabsf(x))) - LN2F;
            *(float2*)&red[(row0 + 8) * 64 + col] = make_float2(s0, s1);
        }
    }
    __syncthreads();

    // Per-site perm sums. Sites can straddle tile boundaries -> <=2 atomic
    // contributions per output; float add of 2 terms is order-independent.
    {
        int s0 = R0 / NPERM;
        int s1 = (R0 + valid - 1) / NPERM;
        int nout = (s1 - s0 + 1) * OUTF;
        for (int i = tid; i < nout; i += NTHREADS) {
            int site = s0 + (i >> 6);
            int col  = i & 63;
            int rbeg = max(site * NPERM, R0);
            int rend = min(site * NPERM + NPERM, R0 + valid);
            float v = 0.0f;
            for (int r = rbeg; r < rend; r++)
                v += red[(r - R0) * 64 + col];
            atomicAdd(&out[(long)site * OUTF + col], v);
        }
    }
}

extern "C" void kernel_launch(void* const* d_in, const int* in_sizes, int n_in,
                              void* d_out, int out_size) {
    const float* X  = (const float*)d_in[0];   // X_sites (50000,64) f32
    const int*   NS = (const int*)  d_in[1];   // X_NSs   (50000,12,8) i32
    const float* W  = (const float*)d_in[2];   // W       (64,512) f32
    const float* b  = (const float*)d_in[3];   // b       (64,) f32
    float* out = (float*)d_out;                // (50000,64) f32

    cudaFuncSetAttribute(lcnn_mma_kernel,
                         cudaFuncAttributeMaxDynamicSharedMemorySize, SM_TOTAL);

    split_W_kernel<<<(OUTF * INF + 255) / 256, 256>>>(W);
    split_X_kernel<<<(NSITES * 64 + 255) / 256, 256>>>(X);
    zero_out_kernel<<<(NSITES * OUTF + 255) / 256, 256>>>(out);
    lcnn_mma_kernel<<<NBLOCKS, NTHREADS, SM_TOTAL>>>(NS, b, out);
}